// round 7
// baseline (speedup 1.0000x reference)
#include <cuda_runtime.h>
#include <cstdint>

#define N_NODES 100000
#define N_EDGES 1600000
#define SCAN_BLOCKS 98   // ceil(100000/1024)

// -------- device scratch (static: no allocations allowed) --------
__device__ int   g_deg[N_NODES];
__device__ int   g_rowptr[N_NODES + 1];
__device__ int   g_cursor[N_NODES];
__device__ int   g_col[N_EDGES];
__device__ int   g_bsum[128];
__device__ __align__(16) float g_h1[N_NODES * 128];
// 5 tf32-rounded weight slots: 0:W1a(64x128) 1:W1b(128x128) 2:W2a 3:W2b 4:Wlin(128x64)
__device__ __align__(16) float g_wt[5 * 128 * 128];

__device__ __forceinline__ uint32_t tf32_rna(float x) {
    uint32_t r;
    asm("cvt.rna.tf32.f32 %0, %1;" : "=r"(r) : "f"(x));
    return r;
}

// m16n8k8 tf32 MMA (sm_80+ PTX, works on plain sm_103 target)
__device__ __forceinline__ void mma_tf32(float c[4],
                                         uint32_t a0, uint32_t a1,
                                         uint32_t a2, uint32_t a3,
                                         uint32_t b0, uint32_t b1) {
    asm volatile(
        "mma.sync.aligned.m16n8k8.row.col.f32.tf32.tf32.f32 "
        "{%0,%1,%2,%3}, {%4,%5,%6,%7}, {%8,%9}, {%0,%1,%2,%3};"
        : "+f"(c[0]), "+f"(c[1]), "+f"(c[2]), "+f"(c[3])
        : "r"(a0), "r"(a1), "r"(a2), "r"(a3), "r"(b0), "r"(b1));
}

// MMA over a K-range: A in smem [row][ASTR], W in smem [k][WSTR]
template <int K, int ASTR, int WSTR, int NT>
__device__ __forceinline__ void do_mma(const float* __restrict__ As,
                                       const float* __restrict__ Ws,
                                       float (&acc)[NT][4], int row0, int ch0) {
    int lane = threadIdx.x & 31;
    int g = lane >> 2, tg = lane & 3;
    const float* Ar0 = As + (row0 + g) * ASTR;
    const float* Ar1 = Ar0 + 8 * ASTR;
#pragma unroll
    for (int k0 = 0; k0 < K; k0 += 8) {
        uint32_t a0 = __float_as_uint(Ar0[k0 + tg]);
        uint32_t a1 = __float_as_uint(Ar1[k0 + tg]);
        uint32_t a2 = __float_as_uint(Ar0[k0 + tg + 4]);
        uint32_t a3 = __float_as_uint(Ar1[k0 + tg + 4]);
        const float* B0 = Ws + (k0 + tg) * WSTR + ch0 + g;
        const float* B1 = B0 + 4 * WSTR;
#pragma unroll
        for (int t = 0; t < NT; t++) {
            mma_tf32(acc[t], a0, a1, a2, a3,
                     __float_as_uint(B0[t * 8]), __float_as_uint(B1[t * 8]));
        }
    }
}

// Epilogue -> smem: relu(acc + bias), tf32-rounded (feeds next mma stage)
template <int NT, int MSTR>
__device__ __forceinline__ void st_mid(float* __restrict__ Mi,
                                       float (&acc)[NT][4], int row0, int ch0,
                                       const float* __restrict__ bias) {
    int lane = threadIdx.x & 31;
    int g = lane >> 2, tg = lane & 3;
    int m0 = row0 + g, m1 = m0 + 8;
#pragma unroll
    for (int t = 0; t < NT; t++) {
        int ch = ch0 + t * 8 + 2 * tg;
        float bx = bias[ch], by = bias[ch + 1];
        Mi[m0 * MSTR + ch]     = __uint_as_float(tf32_rna(fmaxf(acc[t][0] + bx, 0.f)));
        Mi[m0 * MSTR + ch + 1] = __uint_as_float(tf32_rna(fmaxf(acc[t][1] + by, 0.f)));
        Mi[m1 * MSTR + ch]     = __uint_as_float(tf32_rna(fmaxf(acc[t][2] + bx, 0.f)));
        Mi[m1 * MSTR + ch + 1] = __uint_as_float(tf32_rna(fmaxf(acc[t][3] + by, 0.f)));
    }
}

// Epilogue -> global: acc + bias (optional relu), float2 stores, row-guarded
template <int NT, int NOUT, bool RELU>
__device__ __forceinline__ void st_glob(float* __restrict__ out,
                                        float (&acc)[NT][4], int grow0, int ch0,
                                        const float* __restrict__ bias, int n) {
    int lane = threadIdx.x & 31;
    int g = lane >> 2, tg = lane & 3;
    int r0 = grow0 + g, r1 = r0 + 8;
#pragma unroll
    for (int t = 0; t < NT; t++) {
        int ch = ch0 + t * 8 + 2 * tg;
        float bx = bias[ch], by = bias[ch + 1];
        float2 v0 = make_float2(acc[t][0] + bx, acc[t][1] + by);
        float2 v1 = make_float2(acc[t][2] + bx, acc[t][3] + by);
        if (RELU) {
            v0.x = fmaxf(v0.x, 0.f); v0.y = fmaxf(v0.y, 0.f);
            v1.x = fmaxf(v1.x, 0.f); v1.y = fmaxf(v1.y, 0.f);
        }
        if (r0 < n) *(float2*)&out[r0 * NOUT + ch] = v0;
        if (r1 < n) *(float2*)&out[r1 * NOUT + ch] = v1;
    }
}

// ==================== init: zero degrees + tf32-round weights ====================
__global__ void k_init(const float* __restrict__ W1a, const float* __restrict__ W1b,
                       const float* __restrict__ W2a, const float* __restrict__ W2b,
                       const float* __restrict__ Wlin) {
    int i = blockIdx.x * 256 + threadIdx.x;
    if (i < N_NODES) g_deg[i] = 0;
    if (i < 65536) {
        int slot, rem;
        if (i < 8192) { slot = 0; rem = i; }
        else if (i < 57344) { slot = 1 + (i - 8192) / 16384; rem = (i - 8192) % 16384; }
        else { slot = 4; rem = i - 57344; }
        const float* Ws = (slot == 0) ? W1a : (slot == 1) ? W1b :
                          (slot == 2) ? W2a : (slot == 3) ? W2b : Wlin;
        g_wt[slot * 16384 + rem] = __uint_as_float(tf32_rna(Ws[rem]));
    }
}

// ==================== CSR build ====================

__global__ void k_degree(const int* __restrict__ ei) {
    int e = blockIdx.x * 256 + threadIdx.x;
    if (e < N_EDGES) atomicAdd(&g_deg[ei[N_EDGES + e]], 1);
}

__global__ void k_scan1() {
    __shared__ int s[1024];
    int t = threadIdx.x;
    int i = blockIdx.x * 1024 + t;
    int v = (i < N_NODES) ? g_deg[i] : 0;
    s[t] = v;
    __syncthreads();
#pragma unroll
    for (int off = 1; off < 1024; off <<= 1) {
        int tmp = (t >= off) ? s[t - off] : 0;
        __syncthreads();
        s[t] += tmp;
        __syncthreads();
    }
    if (i < N_NODES) g_rowptr[i] = s[t] - v;
    if (t == 1023) g_bsum[blockIdx.x] = s[1023];
}

__global__ void k_scan2() {
    __shared__ int s[128];
    int t = threadIdx.x;
    int v = (t < SCAN_BLOCKS) ? g_bsum[t] : 0;
    s[t] = v;
    __syncthreads();
#pragma unroll
    for (int off = 1; off < 128; off <<= 1) {
        int u = (t >= off) ? s[t - off] : 0;
        __syncthreads();
        s[t] += u;
        __syncthreads();
    }
    if (t < SCAN_BLOCKS) g_bsum[t] = s[t] - v;   // exclusive
}

__global__ void k_scan3() {
    int i = blockIdx.x * 256 + threadIdx.x;
    if (i < N_NODES) {
        int r = g_rowptr[i] + g_bsum[i >> 10];
        g_rowptr[i] = r;
        g_cursor[i] = r;
    }
    if (i == 0) g_rowptr[N_NODES] = N_EDGES;
}

__global__ void k_fill(const int* __restrict__ ei) {
    int e = blockIdx.x * 256 + threadIdx.x;
    if (e < N_EDGES) {
        int d = ei[N_EDGES + e];
        int s = ei[e];
        int p = atomicAdd(&g_cursor[d], 1);
        g_col[p] = s;
    }
}

// ==================== Fused conv kernels ====================
// 512 threads = 16 warps. Gather aggregation feeds stage-1 A tile in SMEM.
// MMA phases: row strip r = w&7 (16 rows), col half c = w>>3.

// conv1 fused: h1 = relu( relu((x+agg(x)) @ W1a + b1a) @ W1b + b1b )
__global__ void __launch_bounds__(512, 1)
k_fused1(const float* __restrict__ x,
         const float* __restrict__ b1a, const float* __restrict__ b1b, int n) {
    extern __shared__ float sm[];
    float* A  = sm;                      // 128 x 68   (agg tile, tf32)
    float* Wa = A + 128 * 68;            // 64 x 132
    float* Wb = Wa + 64 * 132;           // 128 x 132
    float* Mi = Wb + 128 * 132;          // 128 x 132  (mid)

    int tid = threadIdx.x;
    int m0 = blockIdx.x * 128;
    int w = tid >> 5, lane = tid & 31;

    // Weight fills (independent of gather; single sync covers both)
    const float4* Wa4 = (const float4*)(g_wt + 0 * 16384);
    for (int i = tid; i < 64 * 32; i += 512) {
        int k = i >> 5, n4 = i & 31;
        *(float4*)&Wa[k * 132 + n4 * 4] = Wa4[i];
    }
    const float4* Wb4 = (const float4*)(g_wt + 1 * 16384);
    for (int i = tid; i < 128 * 32; i += 512) {
        int k = i >> 5, n4 = i & 31;
        *(float4*)&Wb[k * 132 + n4 * 4] = Wb4[i];
    }

    // Gather: warp w handles rows 8w..8w+7; half-warp edge interleave (d=64)
    {
        int c = lane & 15, h = lane >> 4;
        const float4* x4 = (const float4*)x;
#pragma unroll
        for (int r = 0; r < 8; r++) {
            int row = w * 8 + r;
            int node = m0 + row;
            float4 acc = make_float4(0.f, 0.f, 0.f, 0.f);
            if (node < n) {
                int beg = __ldg(&g_rowptr[node]), end = __ldg(&g_rowptr[node + 1]);
                for (int p = beg + h; p < end; p += 2) {
                    int s = __ldg(&g_col[p]);
                    float4 v = x4[s * 16 + c];
                    acc.x += v.x; acc.y += v.y; acc.z += v.z; acc.w += v.w;
                }
            }
            acc.x += __shfl_xor_sync(0xffffffffu, acc.x, 16);
            acc.y += __shfl_xor_sync(0xffffffffu, acc.y, 16);
            acc.z += __shfl_xor_sync(0xffffffffu, acc.z, 16);
            acc.w += __shfl_xor_sync(0xffffffffu, acc.w, 16);
            if (h == 0) {
                uint4 u = {0u, 0u, 0u, 0u};
                if (node < n) {
                    float4 xi = x4[node * 16 + c];
                    u.x = tf32_rna(xi.x + acc.x);
                    u.y = tf32_rna(xi.y + acc.y);
                    u.z = tf32_rna(xi.z + acc.z);
                    u.w = tf32_rna(xi.w + acc.w);
                }
                *(uint4*)&A[row * 68 + c * 4] = u;
            }
        }
    }
    __syncthreads();

    int row0 = (w & 7) * 16;
    int ch0 = (w >> 3) * 64;

    float acc[8][4];
#pragma unroll
    for (int t = 0; t < 8; t++)
        acc[t][0] = acc[t][1] = acc[t][2] = acc[t][3] = 0.f;
    do_mma<64, 68, 132, 8>(A, Wa, acc, row0, ch0);
    __syncthreads();
    st_mid<8, 132>(Mi, acc, row0, ch0, b1a);
    __syncthreads();

    float acc2[8][4];
#pragma unroll
    for (int t = 0; t < 8; t++)
        acc2[t][0] = acc2[t][1] = acc2[t][2] = acc2[t][3] = 0.f;
    do_mma<128, 132, 132, 8>(Mi, Wb, acc2, row0, ch0);
    st_glob<8, 128, true>(g_h1, acc2, m0 + row0, ch0, b1b, n);
}

// conv2 + final fused: out = relu(relu((h1+agg(h1))@W2a+b2a)@W2b+b2b) @ Wlin + blin
__global__ void __launch_bounds__(512, 1)
k_fused2(const float* __restrict__ b2a, const float* __restrict__ b2b,
         const float* __restrict__ blin, float* __restrict__ out, int n) {
    extern __shared__ float sm[];
    float* RA = sm;                  // 128 x 132 : agg tile -> h
    float* RB = RA + 128 * 132;      // 128 x 132 : W2a -> mid -> Wlin(128x68)
    float* RC = RB + 128 * 132;      // 128 x 132 : W2b

    int tid = threadIdx.x;
    int m0 = blockIdx.x * 128;
    int w = tid >> 5, lane = tid & 31;

    // Weight fills
    const float4* W2a4 = (const float4*)(g_wt + 2 * 16384);
    for (int i = tid; i < 128 * 32; i += 512) {
        int k = i >> 5, n4 = i & 31;
        *(float4*)&RB[k * 132 + n4 * 4] = W2a4[i];
    }
    const float4* W2b4 = (const float4*)(g_wt + 3 * 16384);
    for (int i = tid; i < 128 * 32; i += 512) {
        int k = i >> 5, n4 = i & 31;
        *(float4*)&RC[k * 132 + n4 * 4] = W2b4[i];
    }

    // Gather: warp per row, full 32-lane float4 coverage (d=128), unroll 2
    {
        const float4* h4 = (const float4*)g_h1;
#pragma unroll
        for (int r = 0; r < 8; r++) {
            int row = w * 8 + r;
            int node = m0 + row;
            uint4 u = {0u, 0u, 0u, 0u};
            if (node < n) {
                int beg = __ldg(&g_rowptr[node]), end = __ldg(&g_rowptr[node + 1]);
                float4 a0 = make_float4(0.f, 0.f, 0.f, 0.f);
                float4 a1 = make_float4(0.f, 0.f, 0.f, 0.f);
                int p = beg;
                for (; p + 1 < end; p += 2) {
                    int s0 = __ldg(&g_col[p]);
                    int s1 = __ldg(&g_col[p + 1]);
                    float4 v0 = h4[s0 * 32 + lane];
                    float4 v1 = h4[s1 * 32 + lane];
                    a0.x += v0.x; a0.y += v0.y; a0.z += v0.z; a0.w += v0.w;
                    a1.x += v1.x; a1.y += v1.y; a1.z += v1.z; a1.w += v1.w;
                }
                if (p < end) {
                    int s0 = __ldg(&g_col[p]);
                    float4 v0 = h4[s0 * 32 + lane];
                    a0.x += v0.x; a0.y += v0.y; a0.z += v0.z; a0.w += v0.w;
                }
                float4 hi = h4[node * 32 + lane];
                u.x = tf32_rna(hi.x + a0.x + a1.x);
                u.y = tf32_rna(hi.y + a0.y + a1.y);
                u.z = tf32_rna(hi.z + a0.z + a1.z);
                u.w = tf32_rna(hi.w + a0.w + a1.w);
            }
            *(uint4*)&RA[row * 132 + lane * 4] = u;
        }
    }
    __syncthreads();

    int row0 = (w & 7) * 16;
    int ch0 = (w >> 3) * 64;

    // stage 1: mid = relu(agg @ W2a + b2a)
    float acc[8][4];
#pragma unroll
    for (int t = 0; t < 8; t++)
        acc[t][0] = acc[t][1] = acc[t][2] = acc[t][3] = 0.f;
    do_mma<128, 132, 132, 8>(RA, RB, acc, row0, ch0);
    __syncthreads();                 // all reads of RB (W2a) done
    st_mid<8, 132>(RB, acc, row0, ch0, b2a);
    __syncthreads();

    // stage 2: h = relu(mid @ W2b + b2b)
    float acc2[8][4];
#pragma unroll
    for (int t = 0; t < 8; t++)
        acc2[t][0] = acc2[t][1] = acc2[t][2] = acc2[t][3] = 0.f;
    do_mma<128, 132, 132, 8>(RB, RC, acc2, row0, ch0);
    __syncthreads();                 // all reads of RA (stage1 A) + RB (mid) done
    st_mid<8, 132>(RA, acc2, row0, ch0, b2b);   // h -> RA (tf32, relu)
    // load Wlin (128x64, stride 68) into RB
    const float4* Wl4 = (const float4*)(g_wt + 4 * 16384);
    for (int i = tid; i < 128 * 16; i += 512) {
        int k = i >> 4, n4 = i & 15;
        *(float4*)&RB[k * 68 + n4 * 4] = Wl4[i];
    }
    __syncthreads();

    // stage 3: out = h @ Wlin + blin   (NOUT=64, col half = 32, NT=4)
    int ch3 = (w >> 3) * 32;
    float acc3[4][4];
#pragma unroll
    for (int t = 0; t < 4; t++)
        acc3[t][0] = acc3[t][1] = acc3[t][2] = acc3[t][3] = 0.f;
    do_mma<128, 132, 68, 4>(RA, RB, acc3, row0, ch3);
    st_glob<4, 64, false>(out, acc3, m0 + row0, ch3, blin, n);
}

// ==================== host orchestration ====================

extern "C" void kernel_launch(void* const* d_in, const int* in_sizes, int n_in,
                              void* d_out, int out_size) {
    const float* x    = (const float*)d_in[0];
    const int*   ei   = (const int*)d_in[1];
    const float* W1a  = (const float*)d_in[2];
    const float* b1a  = (const float*)d_in[3];
    const float* W1b  = (const float*)d_in[4];
    const float* b1b  = (const float*)d_in[5];
    const float* W2a  = (const float*)d_in[6];
    const float* b2a  = (const float*)d_in[7];
    const float* W2b  = (const float*)d_in[8];
    const float* b2b  = (const float*)d_in[9];
    const float* Wlin = (const float*)d_in[10];
    const float* blin = (const float*)d_in[11];
    float*       out  = (float*)d_out;

    const int SM1 = (128 * 68 + 64 * 132 + 128 * 132 + 128 * 132) * 4;  // 203776
    const int SM2 = (3 * 128 * 132) * 4;                                // 202752
    cudaFuncSetAttribute(k_fused1, cudaFuncAttributeMaxDynamicSharedMemorySize, SM1);
    cudaFuncSetAttribute(k_fused2, cudaFuncAttributeMaxDynamicSharedMemorySize, SM2);

    const int GN = (N_NODES + 255) / 256;   // 391
    const int GE = (N_EDGES + 255) / 256;   // 6250
    const int GB = (N_NODES + 127) / 128;   // 782

    // --- init + CSR build ---
    k_init<<<GN, 256>>>(W1a, W1b, W2a, W2b, Wlin);
    k_degree<<<GE, 256>>>(ei);
    k_scan1<<<SCAN_BLOCKS, 1024>>>();
    k_scan2<<<1, 128>>>();
    k_scan3<<<GN, 256>>>();
    k_fill<<<GE, 256>>>(ei);

    // --- conv1 (gather + MLP fused) ---
    k_fused1<<<GB, 512, SM1>>>(x, b1a, b1b, N_NODES);

    // --- conv2 + final projection (gather + MLP + lin fused) ---
    k_fused2<<<GB, 512, SM2>>>(b2a, b2b, blin, out, N_NODES);
}

// round 8
// speedup vs baseline: 1.2014x; 1.2014x over previous
#include <cuda_runtime.h>
#include <cuda_fp16.h>
#include <cstdint>

#define N_NODES 100000
#define N_EDGES 1600000
#define SCAN_BLOCKS 98   // ceil(100000/1024)

// -------- device scratch (static: no allocations allowed) --------
__device__ int   g_deg[N_NODES];
__device__ int   g_rowptr[N_NODES + 1];
__device__ int   g_cursor[N_NODES];
__device__ int   g_col[N_EDGES];
__device__ int   g_bsum[128];
__device__ __align__(16) __half2 g_x16[N_NODES * 32];   // x in fp16 (64 ch)
__device__ __align__(16) __half2 g_h16[N_NODES * 64];   // h1 in fp16 (128 ch)
__device__ __align__(16) float g_z1[N_NODES * 64];
__device__ __align__(16) float g_z2[N_NODES * 128];
// 5 tf32-rounded weight slots: 0:W1a(64x128) 1:W1b(128x128) 2:W2a 3:W2b 4:Wlin(128x64)
__device__ __align__(16) float g_wt[5 * 128 * 128];

__device__ __forceinline__ uint32_t tf32_rna(float x) {
    uint32_t r;
    asm("cvt.rna.tf32.f32 %0, %1;" : "=r"(r) : "f"(x));
    return r;
}

// m16n8k8 tf32 MMA (sm_80+ PTX, works on plain sm_103 target)
__device__ __forceinline__ void mma_tf32(float c[4],
                                         uint32_t a0, uint32_t a1,
                                         uint32_t a2, uint32_t a3,
                                         uint32_t b0, uint32_t b1) {
    asm volatile(
        "mma.sync.aligned.m16n8k8.row.col.f32.tf32.tf32.f32 "
        "{%0,%1,%2,%3}, {%4,%5,%6,%7}, {%8,%9}, {%0,%1,%2,%3};"
        : "+f"(c[0]), "+f"(c[1]), "+f"(c[2]), "+f"(c[3])
        : "r"(a0), "r"(a1), "r"(a2), "r"(a3), "r"(b0), "r"(b1));
}

// MMA over a K-range: A in smem [row][ASTR], W in smem [k][WSTR]
template <int K, int ASTR, int WSTR, int NT>
__device__ __forceinline__ void do_mma(const float* __restrict__ As,
                                       const float* __restrict__ Ws,
                                       float (&acc)[NT][4], int row0, int ch0) {
    int lane = threadIdx.x & 31;
    int g = lane >> 2, tg = lane & 3;
    const float* Ar0 = As + (row0 + g) * ASTR;
    const float* Ar1 = Ar0 + 8 * ASTR;
#pragma unroll
    for (int k0 = 0; k0 < K; k0 += 8) {
        uint32_t a0 = __float_as_uint(Ar0[k0 + tg]);
        uint32_t a1 = __float_as_uint(Ar1[k0 + tg]);
        uint32_t a2 = __float_as_uint(Ar0[k0 + tg + 4]);
        uint32_t a3 = __float_as_uint(Ar1[k0 + tg + 4]);
        const float* B0 = Ws + (k0 + tg) * WSTR + ch0 + g;
        const float* B1 = B0 + 4 * WSTR;
#pragma unroll
        for (int t = 0; t < NT; t++) {
            mma_tf32(acc[t], a0, a1, a2, a3,
                     __float_as_uint(B0[t * 8]), __float_as_uint(B1[t * 8]));
        }
    }
}

// Epilogue -> smem: relu(acc + bias), tf32-rounded (feeds next mma stage)
template <int NT, int MSTR>
__device__ __forceinline__ void st_mid(float* __restrict__ Mi,
                                       float (&acc)[NT][4], int row0, int ch0,
                                       const float* __restrict__ bias) {
    int lane = threadIdx.x & 31;
    int g = lane >> 2, tg = lane & 3;
    int m0 = row0 + g, m1 = m0 + 8;
#pragma unroll
    for (int t = 0; t < NT; t++) {
        int ch = ch0 + t * 8 + 2 * tg;
        float bx = bias[ch], by = bias[ch + 1];
        Mi[m0 * MSTR + ch]     = __uint_as_float(tf32_rna(fmaxf(acc[t][0] + bx, 0.f)));
        Mi[m0 * MSTR + ch + 1] = __uint_as_float(tf32_rna(fmaxf(acc[t][1] + by, 0.f)));
        Mi[m1 * MSTR + ch]     = __uint_as_float(tf32_rna(fmaxf(acc[t][2] + bx, 0.f)));
        Mi[m1 * MSTR + ch + 1] = __uint_as_float(tf32_rna(fmaxf(acc[t][3] + by, 0.f)));
    }
}

// Epilogue -> global fp32: acc + bias (optional relu), float2 stores, row-guarded
template <int NT, int NOUT, bool RELU>
__device__ __forceinline__ void st_glob(float* __restrict__ out,
                                        float (&acc)[NT][4], int grow0, int ch0,
                                        const float* __restrict__ bias, int n) {
    int lane = threadIdx.x & 31;
    int g = lane >> 2, tg = lane & 3;
    int r0 = grow0 + g, r1 = r0 + 8;
#pragma unroll
    for (int t = 0; t < NT; t++) {
        int ch = ch0 + t * 8 + 2 * tg;
        float bx = bias[ch], by = bias[ch + 1];
        float2 v0 = make_float2(acc[t][0] + bx, acc[t][1] + by);
        float2 v1 = make_float2(acc[t][2] + bx, acc[t][3] + by);
        if (RELU) {
            v0.x = fmaxf(v0.x, 0.f); v0.y = fmaxf(v0.y, 0.f);
            v1.x = fmaxf(v1.x, 0.f); v1.y = fmaxf(v1.y, 0.f);
        }
        if (r0 < n) *(float2*)&out[r0 * NOUT + ch] = v0;
        if (r1 < n) *(float2*)&out[r1 * NOUT + ch] = v1;
    }
}

// Epilogue -> global fp16 (h1): relu(acc + bias) as half2, row-guarded
template <int NT>
__device__ __forceinline__ void st_glob_h16(__half2* __restrict__ out,
                                            float (&acc)[NT][4], int grow0, int ch0,
                                            const float* __restrict__ bias, int n) {
    int lane = threadIdx.x & 31;
    int g = lane >> 2, tg = lane & 3;
    int r0 = grow0 + g, r1 = r0 + 8;
#pragma unroll
    for (int t = 0; t < NT; t++) {
        int ch = ch0 + t * 8 + 2 * tg;      // even
        float bx = bias[ch], by = bias[ch + 1];
        float2 v0 = make_float2(fmaxf(acc[t][0] + bx, 0.f), fmaxf(acc[t][1] + by, 0.f));
        float2 v1 = make_float2(fmaxf(acc[t][2] + bx, 0.f), fmaxf(acc[t][3] + by, 0.f));
        if (r0 < n) out[r0 * 64 + (ch >> 1)] = __floats2half2_rn(v0.x, v0.y);
        if (r1 < n) out[r1 * 64 + (ch >> 1)] = __floats2half2_rn(v1.x, v1.y);
    }
}

// ==================== init: zero degrees + tf32-round weights ====================
__global__ void k_init(const float* __restrict__ W1a, const float* __restrict__ W1b,
                       const float* __restrict__ W2a, const float* __restrict__ W2b,
                       const float* __restrict__ Wlin) {
    int i = blockIdx.x * 256 + threadIdx.x;
    if (i < N_NODES) g_deg[i] = 0;
    if (i < 65536) {
        int slot, rem;
        if (i < 8192) { slot = 0; rem = i; }
        else if (i < 57344) { slot = 1 + (i - 8192) / 16384; rem = (i - 8192) % 16384; }
        else { slot = 4; rem = i - 57344; }
        const float* Ws = (slot == 0) ? W1a : (slot == 1) ? W1b :
                          (slot == 2) ? W2a : (slot == 3) ? W2b : Wlin;
        g_wt[slot * 16384 + rem] = __uint_as_float(tf32_rna(Ws[rem]));
    }
}

// ==================== CSR build (+ x -> fp16 convert, same grid) ====================

__global__ void k_degree(const int* __restrict__ ei, const float* __restrict__ x) {
    int e = blockIdx.x * 256 + threadIdx.x;     // 1.6M threads
    if (e < N_EDGES) atomicAdd(&g_deg[ei[N_EDGES + e]], 1);
    // convert x (6.4M floats) to fp16: thread e handles float4 e
    const float4* x4 = (const float4*)x;
    float4 v = x4[e];                            // e < 1.6M exactly covers x
    g_x16[e * 2]     = __floats2half2_rn(v.x, v.y);
    g_x16[e * 2 + 1] = __floats2half2_rn(v.z, v.w);
}

__global__ void k_scan1() {
    __shared__ int s[1024];
    int t = threadIdx.x;
    int i = blockIdx.x * 1024 + t;
    int v = (i < N_NODES) ? g_deg[i] : 0;
    s[t] = v;
    __syncthreads();
#pragma unroll
    for (int off = 1; off < 1024; off <<= 1) {
        int tmp = (t >= off) ? s[t - off] : 0;
        __syncthreads();
        s[t] += tmp;
        __syncthreads();
    }
    if (i < N_NODES) g_rowptr[i] = s[t] - v;
    if (t == 1023) g_bsum[blockIdx.x] = s[1023];
}

__global__ void k_scan2() {
    __shared__ int s[128];
    int t = threadIdx.x;
    int v = (t < SCAN_BLOCKS) ? g_bsum[t] : 0;
    s[t] = v;
    __syncthreads();
#pragma unroll
    for (int off = 1; off < 128; off <<= 1) {
        int u = (t >= off) ? s[t - off] : 0;
        __syncthreads();
        s[t] += u;
        __syncthreads();
    }
    if (t < SCAN_BLOCKS) g_bsum[t] = s[t] - v;   // exclusive
}

__global__ void k_scan3() {
    int i = blockIdx.x * 256 + threadIdx.x;
    if (i < N_NODES) {
        int r = g_rowptr[i] + g_bsum[i >> 10];
        g_rowptr[i] = r;
        g_cursor[i] = r;
    }
    if (i == 0) g_rowptr[N_NODES] = N_EDGES;
}

__global__ void k_fill(const int* __restrict__ ei) {
    int e = blockIdx.x * 256 + threadIdx.x;
    if (e < N_EDGES) {
        int d = ei[N_EDGES + e];
        int s = ei[e];
        int p = atomicAdd(&g_cursor[d], 1);
        g_col[p] = s;
    }
}

// ==================== Aggregation (fp16 gather, fp32 accumulate) ====================

// d=64: warp per node; 16 lanes cover 16 uint2 (4 ch each) = one 128B line/edge;
// two half-warps alternate edges, shfl-combined. Self term from fp32 x.
__global__ void __launch_bounds__(256) k_agg64(const float* __restrict__ x) {
    int node = (blockIdx.x * 256 + threadIdx.x) >> 5;
    int lane = threadIdx.x & 31;
    int c = lane & 15;
    int h = lane >> 4;
    int beg = g_rowptr[node], end = g_rowptr[node + 1];
    float4 acc = make_float4(0.f, 0.f, 0.f, 0.f);
    const uint2* x16 = (const uint2*)g_x16;
    for (int p = beg + h; p < end; p += 2) {
        int s = __ldg(&g_col[p]);
        uint2 u = x16[s * 16 + c];
        float2 f0 = __half22float2(*(__half2*)&u.x);
        float2 f1 = __half22float2(*(__half2*)&u.y);
        acc.x += f0.x; acc.y += f0.y; acc.z += f1.x; acc.w += f1.y;
    }
    acc.x += __shfl_xor_sync(0xffffffffu, acc.x, 16);
    acc.y += __shfl_xor_sync(0xffffffffu, acc.y, 16);
    acc.z += __shfl_xor_sync(0xffffffffu, acc.z, 16);
    acc.w += __shfl_xor_sync(0xffffffffu, acc.w, 16);
    if (h == 0) {
        float4 xi = ((const float4*)x)[node * 16 + c];
        ((float4*)g_z1)[node * 16 + c] =
            make_float4(xi.x + acc.x, xi.y + acc.y, xi.z + acc.z, xi.w + acc.w);
    }
}

// d=128: warp per node; 32 lanes cover 32 uint2 = 256B/edge; unroll 2.
__global__ void __launch_bounds__(256) k_agg128() {
    int node = (blockIdx.x * 256 + threadIdx.x) >> 5;
    int lane = threadIdx.x & 31;
    int beg = g_rowptr[node], end = g_rowptr[node + 1];
    const uint2* h16 = (const uint2*)g_h16;
    float4 a0 = make_float4(0.f, 0.f, 0.f, 0.f);
    float4 a1 = make_float4(0.f, 0.f, 0.f, 0.f);
    int p = beg;
    for (; p + 1 < end; p += 2) {
        int s0 = __ldg(&g_col[p]);
        int s1 = __ldg(&g_col[p + 1]);
        uint2 u0 = h16[s0 * 32 + lane];
        uint2 u1 = h16[s1 * 32 + lane];
        float2 f00 = __half22float2(*(__half2*)&u0.x);
        float2 f01 = __half22float2(*(__half2*)&u0.y);
        float2 f10 = __half22float2(*(__half2*)&u1.x);
        float2 f11 = __half22float2(*(__half2*)&u1.y);
        a0.x += f00.x; a0.y += f00.y; a0.z += f01.x; a0.w += f01.y;
        a1.x += f10.x; a1.y += f10.y; a1.z += f11.x; a1.w += f11.y;
    }
    if (p < end) {
        int s0 = __ldg(&g_col[p]);
        uint2 u0 = h16[s0 * 32 + lane];
        float2 f00 = __half22float2(*(__half2*)&u0.x);
        float2 f01 = __half22float2(*(__half2*)&u0.y);
        a0.x += f00.x; a0.y += f00.y; a0.z += f01.x; a0.w += f01.y;
    }
    uint2 us = h16[node * 32 + lane];
    float2 s0 = __half22float2(*(__half2*)&us.x);
    float2 s1 = __half22float2(*(__half2*)&us.y);
    ((float4*)g_z2)[node * 32 + lane] =
        make_float4(s0.x + a0.x + a1.x, s0.y + a0.y + a1.y,
                    s1.x + a0.z + a1.z, s1.y + a0.w + a1.w);
}

// ==================== Fused MLP kernels ====================
// 512 threads = 16 warps: row strip r = w&7 (16 rows), col half c = w>>3.

// conv1: h1(fp16) = relu( relu(z1@W1a+b1a) @ W1b + b1b )
__global__ void __launch_bounds__(512, 1)
k_mlp1(const float* __restrict__ b1a, const float* __restrict__ b1b, int n) {
    extern __shared__ float sm[];
    float* A  = sm;                      // 128 x 68   (z1 tile, tf32)
    float* Wa = A + 128 * 68;            // 64 x 132
    float* Wb = Wa + 64 * 132;           // 128 x 132
    float* Mi = Wb + 128 * 132;          // 128 x 132  (mid)

    int tid = threadIdx.x;
    int m0 = blockIdx.x * 128;

    const float4* in4 = (const float4*)g_z1;
    for (int i = tid; i < 128 * 16; i += 512) {
        int row = i >> 4, k4 = i & 15;
        int node = m0 + row;
        float4 v = (node < n) ? in4[node * 16 + k4] : make_float4(0.f, 0.f, 0.f, 0.f);
        uint4 u;
        u.x = tf32_rna(v.x); u.y = tf32_rna(v.y);
        u.z = tf32_rna(v.z); u.w = tf32_rna(v.w);
        *(uint4*)&A[row * 68 + k4 * 4] = u;
    }
    const float4* Wa4 = (const float4*)(g_wt + 0 * 16384);
    for (int i = tid; i < 64 * 32; i += 512) {
        int k = i >> 5, n4 = i & 31;
        *(float4*)&Wa[k * 132 + n4 * 4] = Wa4[i];
    }
    const float4* Wb4 = (const float4*)(g_wt + 1 * 16384);
    for (int i = tid; i < 128 * 32; i += 512) {
        int k = i >> 5, n4 = i & 31;
        *(float4*)&Wb[k * 132 + n4 * 4] = Wb4[i];
    }
    __syncthreads();

    int w = tid >> 5;
    int row0 = (w & 7) * 16;
    int ch0 = (w >> 3) * 64;

    float acc[8][4];
#pragma unroll
    for (int t = 0; t < 8; t++)
        acc[t][0] = acc[t][1] = acc[t][2] = acc[t][3] = 0.f;
    do_mma<64, 68, 132, 8>(A, Wa, acc, row0, ch0);
    __syncthreads();
    st_mid<8, 132>(Mi, acc, row0, ch0, b1a);
    __syncthreads();

    float acc2[8][4];
#pragma unroll
    for (int t = 0; t < 8; t++)
        acc2[t][0] = acc2[t][1] = acc2[t][2] = acc2[t][3] = 0.f;
    do_mma<128, 132, 132, 8>(Mi, Wb, acc2, row0, ch0);
    st_glob_h16<8>(g_h16, acc2, m0 + row0, ch0, b1b, n);
}

// conv2 + final: out = relu( relu(z2@W2a+b2a) @ W2b + b2b ) @ Wlin + blin
__global__ void __launch_bounds__(512, 1)
k_mlp2(const float* __restrict__ b2a, const float* __restrict__ b2b,
       const float* __restrict__ blin, float* __restrict__ out, int n) {
    extern __shared__ float sm[];
    float* RA = sm;                  // 128 x 132 : z2 tile -> h
    float* RB = RA + 128 * 132;      // 128 x 132 : W2a -> mid -> Wlin(128x68)
    float* RC = RB + 128 * 132;      // 128 x 132 : W2b

    int tid = threadIdx.x;
    int m0 = blockIdx.x * 128;

    const float4* in4 = (const float4*)g_z2;
    for (int i = tid; i < 128 * 32; i += 512) {
        int row = i >> 5, k4 = i & 31;
        int node = m0 + row;
        float4 v = (node < n) ? in4[node * 32 + k4] : make_float4(0.f, 0.f, 0.f, 0.f);
        uint4 u;
        u.x = tf32_rna(v.x); u.y = tf32_rna(v.y);
        u.z = tf32_rna(v.z); u.w = tf32_rna(v.w);
        *(uint4*)&RA[row * 132 + k4 * 4] = u;
    }
    const float4* W2a4 = (const float4*)(g_wt + 2 * 16384);
    for (int i = tid; i < 128 * 32; i += 512) {
        int k = i >> 5, n4 = i & 31;
        *(float4*)&RB[k * 132 + n4 * 4] = W2a4[i];
    }
    const float4* W2b4 = (const float4*)(g_wt + 3 * 16384);
    for (int i = tid; i < 128 * 32; i += 512) {
        int k = i >> 5, n4 = i & 31;
        *(float4*)&RC[k * 132 + n4 * 4] = W2b4[i];
    }
    __syncthreads();

    int w = tid >> 5;
    int row0 = (w & 7) * 16;
    int ch0 = (w >> 3) * 64;

    // stage 1: mid = relu(z2 @ W2a + b2a)
    float acc[8][4];
#pragma unroll
    for (int t = 0; t < 8; t++)
        acc[t][0] = acc[t][1] = acc[t][2] = acc[t][3] = 0.f;
    do_mma<128, 132, 132, 8>(RA, RB, acc, row0, ch0);
    __syncthreads();
    st_mid<8, 132>(RB, acc, row0, ch0, b2a);
    __syncthreads();

    // stage 2: h = relu(mid @ W2b + b2b)
    float acc2[8][4];
#pragma unroll
    for (int t = 0; t < 8; t++)
        acc2[t][0] = acc2[t][1] = acc2[t][2] = acc2[t][3] = 0.f;
    do_mma<128, 132, 132, 8>(RB, RC, acc2, row0, ch0);
    __syncthreads();
    st_mid<8, 132>(RA, acc2, row0, ch0, b2b);   // h -> RA (tf32, relu)
    // load Wlin (128x64, stride 68) into RB
    const float4* Wl4 = (const float4*)(g_wt + 4 * 16384);
    for (int i = tid; i < 128 * 16; i += 512) {
        int k = i >> 4, n4 = i & 15;
        *(float4*)&RB[k * 68 + n4 * 4] = Wl4[i];
    }
    __syncthreads();

    // stage 3: out = h @ Wlin + blin   (NOUT=64, col half = 32, NT=4)
    int ch3 = (w >> 3) * 32;
    float acc3[4][4];
#pragma unroll
    for (int t = 0; t < 4; t++)
        acc3[t][0] = acc3[t][1] = acc3[t][2] = acc3[t][3] = 0.f;
    do_mma<128, 132, 68, 4>(RA, RB, acc3, row0, ch3);
    st_glob<4, 64, false>(out, acc3, m0 + row0, ch3, blin, n);
}

// ==================== host orchestration ====================

extern "C" void kernel_launch(void* const* d_in, const int* in_sizes, int n_in,
                              void* d_out, int out_size) {
    const float* x    = (const float*)d_in[0];
    const int*   ei   = (const int*)d_in[1];
    const float* W1a  = (const float*)d_in[2];
    const float* b1a  = (const float*)d_in[3];
    const float* W1b  = (const float*)d_in[4];
    const float* b1b  = (const float*)d_in[5];
    const float* W2a  = (const float*)d_in[6];
    const float* b2a  = (const float*)d_in[7];
    const float* W2b  = (const float*)d_in[8];
    const float* b2b  = (const float*)d_in[9];
    const float* Wlin = (const float*)d_in[10];
    const float* blin = (const float*)d_in[11];
    float*       out  = (float*)d_out;

    const int SM1 = (128 * 68 + 64 * 132 + 128 * 132 + 128 * 132) * 4;  // 203776
    const int SM2 = (3 * 128 * 132) * 4;                                // 202752
    cudaFuncSetAttribute(k_mlp1, cudaFuncAttributeMaxDynamicSharedMemorySize, SM1);
    cudaFuncSetAttribute(k_mlp2, cudaFuncAttributeMaxDynamicSharedMemorySize, SM2);

    const int GN = (N_NODES + 255) / 256;   // 391
    const int GE = (N_EDGES + 255) / 256;   // 6250
    const int GW = N_NODES / 8;             // 12500
    const int GB = (N_NODES + 127) / 128;   // 782

    // --- init + CSR build (+ x->fp16) ---
    k_init<<<GN, 256>>>(W1a, W1b, W2a, W2b, Wlin);
    k_degree<<<GE, 256>>>(ei, x);
    k_scan1<<<SCAN_BLOCKS, 1024>>>();
    k_scan2<<<1, 128>>>();
    k_scan3<<<GN, 256>>>();
    k_fill<<<GE, 256>>>(ei);

    // --- conv1 ---
    k_agg64<<<GW, 256>>>(x);
    k_mlp1<<<GB, 512, SM1>>>(b1a, b1b, N_NODES);

    // --- conv2 + final projection ---
    k_agg128<<<GW, 256>>>();
    k_mlp2<<<GB, 512, SM2>>>(b2a, b2b, blin, out, N_NODES);
}